// round 6
// baseline (speedup 1.0000x reference)
#include <cuda_runtime.h>
#include <cstdint>
#include <math.h>

// Problem constants
#define NB   64
#define SEQL 512
#define DIN  256
#define NF   256
#define KSZ  3
#define NJ   768                 // KSZ*NF

// Static device scratch (no allocs allowed)
__device__ float g_sig[NB * DIN];                  // sigmoid(z)
__device__ float g_Vr [DIN * NJ];                  // rna(V)            [e][j]
__device__ float g_xr [NB * SEQL * DIN];           // rna(x)            33.5 MB
__device__ float g_Ub [NB * DIN * DIN];            // rna(U * sig_b)    16.8 MB [b][d][e]
__device__ float g_Wt [NB * KSZ * DIN * NF];       // weights           50.3 MB [b][k][d][f]

// ---------------------------------------------------------------------------
// Helpers
// ---------------------------------------------------------------------------
__device__ __forceinline__ uint32_t smem_u32(const void* p) {
    uint32_t a;
    asm("{ .reg .u64 t; cvta.to.shared.u64 t, %1; cvt.u32.u64 %0, t; }"
        : "=r"(a) : "l"(p));
    return a;
}
__device__ __forceinline__ float rna(float x) {
    uint32_t u;
    asm("cvt.rna.tf32.f32 %0, %1;" : "=r"(u) : "f"(x));
    return __uint_as_float(u);
}
#define CP16(dst, src) \
    asm volatile("cp.async.cg.shared.global [%0], [%1], 16;" :: "r"(dst), "l"(src))
#define CP16Z(dst, src, sz) \
    asm volatile("cp.async.cg.shared.global [%0], [%1], 16, %2;" :: "r"(dst), "l"(src), "r"(sz))
#define CP_COMMIT() asm volatile("cp.async.commit_group;")
#define CP_WAIT1()  asm volatile("cp.async.wait_group 1;" ::: "memory")
#define CP_WAIT0()  asm volatile("cp.async.wait_group 0;" ::: "memory")

// ---------------------------------------------------------------------------
// SMEM stage (32 KB; three stages = 96 KB dynamic):
//   As: 128 rows (M) x 32 floats (K), 128 B/row; chunk c4 (0..7) of row r at
//       r*128 + ((c4 ^ (r&7))<<4)                           [16384 B]
//   Bs:  32 rows (K) x 128 floats (N), 512 B/row; chunk c4 (0..31) of row r at
//       r*512 + ((c4 ^ ((2r)&31))<<4)                       [16384 B]
// Fragment-load patterns bank-conflict-free (same maps as round-5 kernel).
// ---------------------------------------------------------------------------
#define STAGE_BYTES 32768
#define NSTAGE      3
#define SMEM_BYTES  (STAGE_BYTES * NSTAGE)

// One BK=32 slab: warp tile 32(M) x 32(N), m16n8k8 tf32, acc[32].
__device__ __forceinline__ void tile_mma(float* __restrict__ acc,
                                         const char* __restrict__ As,
                                         const char* __restrict__ Bs,
                                         int gid, int tig, int wm, int wn)
{
    const int nqb = wn * 8 + (gid >> 2);
    const int na  = (gid & 3) * 4;
    const char* Am = As + (wm * 32 + gid) * 128 + tig * 4;

    #pragma unroll
    for (int ks = 0; ks < 4; ++ks) {
        const int ax0 = ((2 * ks)     ^ gid) << 4;
        const int ax1 = ((2 * ks + 1) ^ gid) << 4;
        uint32_t a[2][4];
        #pragma unroll
        for (int mi = 0; mi < 2; ++mi) {
            const char* bm = Am + mi * 2048;          // +16 rows
            a[mi][0] = *(const uint32_t*)(bm + ax0);
            a[mi][1] = *(const uint32_t*)(bm + 1024 + ax0);   // +8 rows
            a[mi][2] = *(const uint32_t*)(bm + ax1);
            a[mi][3] = *(const uint32_t*)(bm + 1024 + ax1);
        }
        const int kk0 = ks * 8 + tig, kk1 = kk0 + 4;
        const int g0 = (2 * kk0) & 31, g1 = (2 * kk1) & 31;
        const char* Br0 = Bs + kk0 * 512 + na;
        const char* Br1 = Bs + kk1 * 512 + na;
        #pragma unroll
        for (int ni = 0; ni < 4; ++ni) {
            const int nq = nqb + 2 * ni;
            const uint32_t b0 = *(const uint32_t*)(Br0 + ((nq ^ g0) << 4));
            const uint32_t b1 = *(const uint32_t*)(Br1 + ((nq ^ g1) << 4));
            #pragma unroll
            for (int mi = 0; mi < 2; ++mi) {
                float* c = &acc[(mi * 4 + ni) * 4];
                asm volatile(
                    "mma.sync.aligned.m16n8k8.row.col.f32.tf32.tf32.f32 "
                    "{%0,%1,%2,%3}, {%4,%5,%6,%7}, {%8,%9}, {%0,%1,%2,%3};"
                    : "+f"(c[0]), "+f"(c[1]), "+f"(c[2]), "+f"(c[3])
                    : "r"(a[mi][0]), "r"(a[mi][1]), "r"(a[mi][2]), "r"(a[mi][3]),
                      "r"(b0), "r"(b1));
            }
        }
    }
}

// ---------------------------------------------------------------------------
// Prep 1: rna(x) -> g_xr, rna(V) -> g_Vr, sigmoid(z) -> g_sig
// ---------------------------------------------------------------------------
__global__ void prep1(const float* __restrict__ x,
                      const float* __restrict__ z,
                      const float* __restrict__ V)
{
    const int tid = blockIdx.x * blockDim.x + threadIdx.x;
    const int nth = gridDim.x * blockDim.x;
    const float4* x4 = (const float4*)x;
    float4* xr4 = (float4*)g_xr;
    for (int i = tid; i < NB * SEQL * DIN / 4; i += nth) {
        float4 v = x4[i];
        v.x = rna(v.x); v.y = rna(v.y); v.z = rna(v.z); v.w = rna(v.w);
        xr4[i] = v;
    }
    const float4* V4 = (const float4*)V;
    float4* Vr4 = (float4*)g_Vr;
    for (int i = tid; i < DIN * NJ / 4; i += nth) {
        float4 v = V4[i];
        v.x = rna(v.x); v.y = rna(v.y); v.z = rna(v.z); v.w = rna(v.w);
        Vr4[i] = v;
    }
    for (int i = tid; i < NB * DIN; i += nth)
        g_sig[i] = 1.f / (1.f + expf(-z[i]));
}

// ---------------------------------------------------------------------------
// Prep 2: g_Ub[b][d][e] = rna(U[d][e] * sig[b][e])
// ---------------------------------------------------------------------------
__global__ void prep2(const float* __restrict__ U)
{
    const int b = blockIdx.x, dblk = blockIdx.y;
    const int t = threadIdx.x;
    const int d  = dblk * 4 + (t >> 6);
    const int e4 = (t & 63) * 4;
    const float4 u = *(const float4*)(U + (size_t)d * DIN + e4);
    const float4 s = *(const float4*)(g_sig + b * DIN + e4);
    float4 o;
    o.x = rna(u.x * s.x); o.y = rna(u.y * s.y);
    o.z = rna(u.z * s.z); o.w = rna(u.w * s.w);
    *(float4*)(g_Ub + ((size_t)(b * DIN + d)) * DIN + e4) = o;
}

// ---------------------------------------------------------------------------
// GEMM1: per b: D[d][j] = sum_e Ub[b][d][e] * Vr[e][j]; W = D + Bw
//   CTA 128x128, 512 thr (16 warps, 4x4 of 32x32), BK=32, K=256 (8 tiles)
//   store g_Wt[b][k][d][f] (rna-rounded)
// ---------------------------------------------------------------------------
__global__ __launch_bounds__(512)
void gemm_w(const float* __restrict__ Bw)
{
    extern __shared__ char sm[];
    const int b = blockIdx.z, m0 = blockIdx.y * 128, n0 = blockIdx.x * 128;
    const int kq = n0 >> 8, f0 = n0 & 255;
    const int tid = (int)threadIdx.x, wid = tid >> 5, lane = tid & 31;
    const int gid = lane >> 2, tig = lane & 3, wm = wid & 3, wn = wid >> 2;

    const uint32_t sb = smem_u32(sm);
    const float* Asrc = g_Ub + (size_t)b * DIN * DIN + (size_t)m0 * DIN;
    const float* Bsrc = g_Vr + n0;

    float acc[32];
    #pragma unroll
    for (int i = 0; i < 32; ++i) acc[i] = 0.f;

    auto load = [&](int t) {
        const int e0 = t * 32, st = t % NSTAGE;
        const uint32_t ab = sb + st * STAGE_BYTES;
        const uint32_t bb = ab + 16384;
        #pragma unroll
        for (int i = 0; i < 2; ++i) {
            const int c = tid + i * 512;
            const int r = c >> 3, c4 = c & 7;
            CP16(ab + r * 128 + ((c4 ^ (r & 7)) << 4),
                 Asrc + (size_t)r * DIN + e0 + c4 * 4);
        }
        #pragma unroll
        for (int i = 0; i < 2; ++i) {
            const int c = tid + i * 512;
            const int r = c >> 5, c4 = c & 31;
            CP16(bb + r * 512 + ((c4 ^ ((2 * r) & 31)) << 4),
                 Bsrc + (size_t)(e0 + r) * NJ + c4 * 4);
        }
        CP_COMMIT();
    };

    load(0); load(1);
    for (int t = 0; t < 8; ++t) {
        if (t < 7) CP_WAIT1(); else CP_WAIT0();
        __syncthreads();
        if (t + 2 < 8) load(t + 2);
        const char* stg = sm + (t % NSTAGE) * STAGE_BYTES;
        tile_mma(acc, stg, stg + 16384, gid, tig, wm, wn);
    }

    // epilogue: + Bw, rna, store g_Wt[b][kq][d][f]
    #pragma unroll
    for (int mi = 0; mi < 2; ++mi)
        #pragma unroll
        for (int h = 0; h < 2; ++h) {
            const int d = m0 + wm * 32 + mi * 16 + gid + 8 * h;
            float* Wrow = g_Wt + (((size_t)(b * KSZ + kq) * DIN + d) * NF) + f0;
            const float* BwRow = Bw + (size_t)d * NJ + n0;
            #pragma unroll
            for (int ni = 0; ni < 4; ++ni) {
                const int jl = wn * 32 + ni * 8 + 2 * tig;
                const float2 bw = *(const float2*)(BwRow + jl);
                const float* c = &acc[(mi * 4 + ni) * 4 + 2 * h];
                float2 w;
                w.x = rna(c[0] + bw.x);
                w.y = rna(c[1] + bw.y);
                *(float2*)(Wrow + jl) = w;
            }
        }
}

// ---------------------------------------------------------------------------
// Conv: per b: out[l][f] = relu( sum_{kd<768} A[l][kd] * Wt[b][kd][f] + bias )
//   A[l][kd] = g_xr[b] flat at (l-1)*256 + kd, zero outside [0, 512*256)
//   CTA 128x128, 512 thr, BK=32, K=768 (24 tiles)
// ---------------------------------------------------------------------------
__global__ __launch_bounds__(512)
void conv_mma(const float* __restrict__ bias, float* __restrict__ out)
{
    extern __shared__ char sm[];
    const int b = blockIdx.z, l0 = blockIdx.y * 128, f0 = blockIdx.x * 128;
    const int tid = (int)threadIdx.x, wid = tid >> 5, lane = tid & 31;
    const int gid = lane >> 2, tig = lane & 3, wm = wid & 3, wn = wid >> 2;

    const uint32_t sb = smem_u32(sm);
    const float* xb = g_xr + (size_t)b * SEQL * DIN;
    const float* Wb = g_Wt + (size_t)b * KSZ * DIN * NF + f0;

    float acc[32];
    #pragma unroll
    for (int i = 0; i < 32; ++i) acc[i] = 0.f;

    auto load = [&](int t) {
        const int e0 = t * 32, st = t % NSTAGE;
        const uint32_t ab = sb + st * STAGE_BYTES;
        const uint32_t bb = ab + 16384;
        #pragma unroll
        for (int i = 0; i < 2; ++i) {
            const int c = tid + i * 512;
            const int r = c >> 3, c4 = c & 7;
            const int idx = (l0 + r - 1) * DIN + e0 + c4 * 4;
            const unsigned ok = ((unsigned)idx < (unsigned)(SEQL * DIN));
            const float* src = xb + (ok ? idx : 0);
            CP16Z(ab + r * 128 + ((c4 ^ (r & 7)) << 4), src, ok ? 16u : 0u);
        }
        #pragma unroll
        for (int i = 0; i < 2; ++i) {
            const int c = tid + i * 512;
            const int r = c >> 5, c4 = c & 31;
            CP16(bb + r * 512 + ((c4 ^ ((2 * r) & 31)) << 4),
                 Wb + (size_t)(e0 + r) * NF + c4 * 4);
        }
        CP_COMMIT();
    };

    load(0); load(1);
    for (int t = 0; t < 24; ++t) {
        if (t < 23) CP_WAIT1(); else CP_WAIT0();
        __syncthreads();
        if (t + 2 < 24) load(t + 2);
        const char* stg = sm + (t % NSTAGE) * STAGE_BYTES;
        tile_mma(acc, stg, stg + 16384, gid, tig, wm, wn);
    }

    // epilogue: + bias, relu, store (f contiguous)
    #pragma unroll
    for (int mi = 0; mi < 2; ++mi)
        #pragma unroll
        for (int h = 0; h < 2; ++h) {
            const int l = l0 + wm * 32 + mi * 16 + gid + 8 * h;
            float* Orow = out + ((size_t)b * SEQL + l) * NF + f0;
            #pragma unroll
            for (int ni = 0; ni < 4; ++ni) {
                const int fl = wn * 32 + ni * 8 + 2 * tig;
                const float2 bv = *(const float2*)(bias + f0 + fl);
                const float* c = &acc[(mi * 4 + ni) * 4 + 2 * h];
                float2 o;
                o.x = fmaxf(c[0] + bv.x, 0.f);
                o.y = fmaxf(c[1] + bv.y, 0.f);
                *(float2*)(Orow + fl) = o;
            }
        }
}

// ---------------------------------------------------------------------------
// kernel_launch: prep1 -> prep2 -> gemm_w -> conv (stream-ordered, capturable)
// Inputs: x, z, U, V, B_w, b, kernel_size(ignored; KSZ=3)
// ---------------------------------------------------------------------------
extern "C" void kernel_launch(void* const* d_in, const int* in_sizes, int n_in,
                              void* d_out, int out_size)
{
    (void)in_sizes; (void)n_in; (void)out_size;
    const float* x    = (const float*)d_in[0];
    const float* z    = (const float*)d_in[1];
    const float* U    = (const float*)d_in[2];
    const float* V    = (const float*)d_in[3];
    const float* Bw   = (const float*)d_in[4];
    const float* bias = (const float*)d_in[5];
    float* out = (float*)d_out;

    static bool attr_done = false;
    if (!attr_done) {
        cudaFuncSetAttribute(gemm_w,   cudaFuncAttributeMaxDynamicSharedMemorySize, SMEM_BYTES);
        cudaFuncSetAttribute(conv_mma, cudaFuncAttributeMaxDynamicSharedMemorySize, SMEM_BYTES);
        attr_done = true;
    }

    prep1<<<2048, 256>>>(x, z, V);
    prep2<<<dim3(NB, DIN / 4), 256>>>(U);
    gemm_w<<<dim3(NJ / 128, DIN / 128, NB), 512, SMEM_BYTES>>>(Bw);
    conv_mma<<<dim3(NF / 128, SEQL / 128, NB), 512, SMEM_BYTES>>>(bias, out);
}

// round 7
// speedup vs baseline: 1.0503x; 1.0503x over previous
#include <cuda_runtime.h>
#include <cstdint>
#include <math.h>

// Problem constants
#define NB   64
#define SEQL 512
#define DIN  256
#define NF   256
#define KSZ  3
#define NJ   768                 // KSZ*NF

// Static device scratch (no allocs allowed)
__device__ float g_sig[NB * DIN];                  // sigmoid(z)
__device__ float g_Vr [DIN * NJ];                  // rna(V)            [e][j]
__device__ float g_xr [NB * SEQL * DIN];           // rna(x)            33.5 MB
__device__ float g_Ub [NB * DIN * DIN];            // rna(U * sig_b)    16.8 MB [b][d][e]
__device__ float g_Wt [NB * KSZ * DIN * NF];       // weights           50.3 MB [b][k][d][f]

// ---------------------------------------------------------------------------
// Helpers
// ---------------------------------------------------------------------------
__device__ __forceinline__ uint32_t smem_u32(const void* p) {
    uint32_t a;
    asm("{ .reg .u64 t; cvta.to.shared.u64 t, %1; cvt.u32.u64 %0, t; }"
        : "=r"(a) : "l"(p));
    return a;
}
__device__ __forceinline__ float rna(float x) {
    uint32_t u;
    asm("cvt.rna.tf32.f32 %0, %1;" : "=r"(u) : "f"(x));
    return __uint_as_float(u);
}
#define CP16(dst, src) \
    asm volatile("cp.async.cg.shared.global [%0], [%1], 16;" :: "r"(dst), "l"(src))
#define CP16Z(dst, src, sz) \
    asm volatile("cp.async.cg.shared.global [%0], [%1], 16, %2;" :: "r"(dst), "l"(src), "r"(sz))
#define CP_COMMIT() asm volatile("cp.async.commit_group;")
#define CP_WAIT1()  asm volatile("cp.async.wait_group 1;" ::: "memory")
#define CP_WAIT0()  asm volatile("cp.async.wait_group 0;" ::: "memory")

// ---------------------------------------------------------------------------
// SMEM stage (32 KB; three stages = 96 KB dynamic):
//   As: 128 rows (M) x 32 floats (K), 128 B/row; chunk c4 (0..7) of row r at
//       r*128 + ((c4 ^ (r&7))<<4)                           [16384 B]
//   Bs:  32 rows (K) x 128 floats (N), 512 B/row; chunk c4 (0..31) of row r at
//       r*512 + ((c4 ^ ((2r)&31))<<4)                       [16384 B]
// Fragment-load patterns bank-conflict-free (verified maps, round-5 proven).
// ---------------------------------------------------------------------------
#define STAGE_BYTES 32768
#define NSTAGE      3
#define SMEM_BYTES  (STAGE_BYTES * NSTAGE)

// One BK=32 slab: warp tile 32(M) x 64(N), m16n8k8 tf32, acc[64].
// ks loop kept rolled (#pragma unroll 1) to bound live fragment registers.
__device__ __forceinline__ void tile_mma(float* __restrict__ acc,
                                         const char* __restrict__ As,
                                         const char* __restrict__ Bs,
                                         int gid, int tig, int wm, int wn)
{
    const int nqb = wn * 16 + (gid >> 2);
    const int na  = (gid & 3) * 4;
    const char* Am = As + (wm * 32 + gid) * 128 + tig * 4;

    #pragma unroll 1
    for (int ks = 0; ks < 4; ++ks) {
        const int ax0 = ((2 * ks)     ^ gid) << 4;
        const int ax1 = ((2 * ks + 1) ^ gid) << 4;
        uint32_t a[2][4];
        #pragma unroll
        for (int mi = 0; mi < 2; ++mi) {
            const char* bm = Am + mi * 2048;          // +16 rows
            a[mi][0] = *(const uint32_t*)(bm + ax0);
            a[mi][1] = *(const uint32_t*)(bm + 1024 + ax0);   // +8 rows
            a[mi][2] = *(const uint32_t*)(bm + ax1);
            a[mi][3] = *(const uint32_t*)(bm + 1024 + ax1);
        }
        const int kk0 = ks * 8 + tig, kk1 = kk0 + 4;
        const int g0 = (2 * kk0) & 31, g1 = (2 * kk1) & 31;
        const char* Br0 = Bs + kk0 * 512 + na;
        const char* Br1 = Bs + kk1 * 512 + na;
        #pragma unroll
        for (int ni = 0; ni < 8; ++ni) {
            const int nq = nqb + 2 * ni;
            const uint32_t b0 = *(const uint32_t*)(Br0 + ((nq ^ g0) << 4));
            const uint32_t b1 = *(const uint32_t*)(Br1 + ((nq ^ g1) << 4));
            #pragma unroll
            for (int mi = 0; mi < 2; ++mi) {
                float* c = &acc[(mi * 8 + ni) * 4];
                asm volatile(
                    "mma.sync.aligned.m16n8k8.row.col.f32.tf32.tf32.f32 "
                    "{%0,%1,%2,%3}, {%4,%5,%6,%7}, {%8,%9}, {%0,%1,%2,%3};"
                    : "+f"(c[0]), "+f"(c[1]), "+f"(c[2]), "+f"(c[3])
                    : "r"(a[mi][0]), "r"(a[mi][1]), "r"(a[mi][2]), "r"(a[mi][3]),
                      "r"(b0), "r"(b1));
            }
        }
    }
}

// ---------------------------------------------------------------------------
// Prep 1: rna(x) -> g_xr, rna(V) -> g_Vr, sigmoid(z) -> g_sig
// ---------------------------------------------------------------------------
__global__ void prep1(const float* __restrict__ x,
                      const float* __restrict__ z,
                      const float* __restrict__ V)
{
    const int tid = blockIdx.x * blockDim.x + threadIdx.x;
    const int nth = gridDim.x * blockDim.x;
    const float4* x4 = (const float4*)x;
    float4* xr4 = (float4*)g_xr;
    for (int i = tid; i < NB * SEQL * DIN / 4; i += nth) {
        float4 v = x4[i];
        v.x = rna(v.x); v.y = rna(v.y); v.z = rna(v.z); v.w = rna(v.w);
        xr4[i] = v;
    }
    const float4* V4 = (const float4*)V;
    float4* Vr4 = (float4*)g_Vr;
    for (int i = tid; i < DIN * NJ / 4; i += nth) {
        float4 v = V4[i];
        v.x = rna(v.x); v.y = rna(v.y); v.z = rna(v.z); v.w = rna(v.w);
        Vr4[i] = v;
    }
    for (int i = tid; i < NB * DIN; i += nth)
        g_sig[i] = 1.f / (1.f + expf(-z[i]));
}

// ---------------------------------------------------------------------------
// Prep 2: g_Ub[b][d][e] = rna(U[d][e] * sig[b][e])
// ---------------------------------------------------------------------------
__global__ void prep2(const float* __restrict__ U)
{
    const int b = blockIdx.x, dblk = blockIdx.y;
    const int t = threadIdx.x;
    const int d  = dblk * 4 + (t >> 6);
    const int e4 = (t & 63) * 4;
    const float4 u = *(const float4*)(U + (size_t)d * DIN + e4);
    const float4 s = *(const float4*)(g_sig + b * DIN + e4);
    float4 o;
    o.x = rna(u.x * s.x); o.y = rna(u.y * s.y);
    o.z = rna(u.z * s.z); o.w = rna(u.w * s.w);
    *(float4*)(g_Ub + ((size_t)(b * DIN + d)) * DIN + e4) = o;
}

// ---------------------------------------------------------------------------
// GEMM1: per b: D[d][j] = sum_e Ub[b][d][e] * Vr[e][j]; W = D + Bw
//   CTA 128x128, 256 thr (8 warps, 4x2 of 32x64), BK=32, K=256 (8 tiles)
//   store g_Wt[b][k][d][f] (rna-rounded)
// ---------------------------------------------------------------------------
__global__ __launch_bounds__(256, 2)
void gemm_w(const float* __restrict__ Bw)
{
    extern __shared__ char sm[];
    const int b = blockIdx.z, m0 = blockIdx.y * 128, n0 = blockIdx.x * 128;
    const int kq = n0 >> 8, f0 = n0 & 255;
    const int tid = (int)threadIdx.x, wid = tid >> 5, lane = tid & 31;
    const int gid = lane >> 2, tig = lane & 3, wm = wid & 3, wn = wid >> 2;

    const uint32_t sb = smem_u32(sm);
    const float* Asrc = g_Ub + (size_t)b * DIN * DIN + (size_t)m0 * DIN;
    const float* Bsrc = g_Vr + n0;

    float acc[64];
    #pragma unroll
    for (int i = 0; i < 64; ++i) acc[i] = 0.f;

    auto load = [&](int t) {
        const int e0 = t * 32, st = t % NSTAGE;
        const uint32_t ab = sb + st * STAGE_BYTES;
        const uint32_t bb = ab + 16384;
        #pragma unroll
        for (int i = 0; i < 4; ++i) {
            const int c = tid + i * 256;
            const int r = c >> 3, c4 = c & 7;
            CP16(ab + r * 128 + ((c4 ^ (r & 7)) << 4),
                 Asrc + (size_t)r * DIN + e0 + c4 * 4);
        }
        #pragma unroll
        for (int i = 0; i < 4; ++i) {
            const int c = tid + i * 256;
            const int r = c >> 5, c4 = c & 31;
            CP16(bb + r * 512 + ((c4 ^ ((2 * r) & 31)) << 4),
                 Bsrc + (size_t)(e0 + r) * NJ + c4 * 4);
        }
        CP_COMMIT();
    };

    load(0); load(1);
    for (int t = 0; t < 8; ++t) {
        if (t < 7) CP_WAIT1(); else CP_WAIT0();
        __syncthreads();
        if (t + 2 < 8) load(t + 2);
        const char* stg = sm + (t % NSTAGE) * STAGE_BYTES;
        tile_mma(acc, stg, stg + 16384, gid, tig, wm, wn);
    }

    // epilogue: + Bw, rna, store g_Wt[b][kq][d][f]
    #pragma unroll
    for (int mi = 0; mi < 2; ++mi)
        #pragma unroll
        for (int h = 0; h < 2; ++h) {
            const int d = m0 + wm * 32 + mi * 16 + gid + 8 * h;
            float* Wrow = g_Wt + (((size_t)(b * KSZ + kq) * DIN + d) * NF) + f0;
            const float* BwRow = Bw + (size_t)d * NJ + n0;
            #pragma unroll
            for (int ni = 0; ni < 8; ++ni) {
                const int jl = wn * 64 + ni * 8 + 2 * tig;
                const float2 bw = *(const float2*)(BwRow + jl);
                const float* c = &acc[(mi * 8 + ni) * 4 + 2 * h];
                float2 w;
                w.x = rna(c[0] + bw.x);
                w.y = rna(c[1] + bw.y);
                *(float2*)(Wrow + jl) = w;
            }
        }
}

// ---------------------------------------------------------------------------
// Conv: per b: out[l][f] = relu( sum_{kd<768} A[l][kd] * Wt[b][kd][f] + bias )
//   A[l][kd] = g_xr[b] flat at (l-1)*256 + kd, zero outside [0, 512*256)
//   CTA 128x128, 256 thr (8 warps, 4x2 of 32x64), BK=32, K=768 (24 tiles)
// ---------------------------------------------------------------------------
__global__ __launch_bounds__(256, 2)
void conv_mma(const float* __restrict__ bias, float* __restrict__ out)
{
    extern __shared__ char sm[];
    const int b = blockIdx.z, l0 = blockIdx.y * 128, f0 = blockIdx.x * 128;
    const int tid = (int)threadIdx.x, wid = tid >> 5, lane = tid & 31;
    const int gid = lane >> 2, tig = lane & 3, wm = wid & 3, wn = wid >> 2;

    const uint32_t sb = smem_u32(sm);
    const float* xb = g_xr + (size_t)b * SEQL * DIN;
    const float* Wb = g_Wt + (size_t)b * KSZ * DIN * NF + f0;

    float acc[64];
    #pragma unroll
    for (int i = 0; i < 64; ++i) acc[i] = 0.f;

    auto load = [&](int t) {
        const int e0 = t * 32, st = t % NSTAGE;
        const uint32_t ab = sb + st * STAGE_BYTES;
        const uint32_t bb = ab + 16384;
        #pragma unroll
        for (int i = 0; i < 4; ++i) {
            const int c = tid + i * 256;
            const int r = c >> 3, c4 = c & 7;
            const int idx = (l0 + r - 1) * DIN + e0 + c4 * 4;
            const unsigned ok = ((unsigned)idx < (unsigned)(SEQL * DIN));
            const float* src = xb + (ok ? idx : 0);
            CP16Z(ab + r * 128 + ((c4 ^ (r & 7)) << 4), src, ok ? 16u : 0u);
        }
        #pragma unroll
        for (int i = 0; i < 4; ++i) {
            const int c = tid + i * 256;
            const int r = c >> 5, c4 = c & 31;
            CP16(bb + r * 512 + ((c4 ^ ((2 * r) & 31)) << 4),
                 Wb + (size_t)(e0 + r) * NF + c4 * 4);
        }
        CP_COMMIT();
    };

    load(0); load(1);
    for (int t = 0; t < 24; ++t) {
        if (t < 23) CP_WAIT1(); else CP_WAIT0();
        __syncthreads();
        if (t + 2 < 24) load(t + 2);
        const char* stg = sm + (t % NSTAGE) * STAGE_BYTES;
        tile_mma(acc, stg, stg + 16384, gid, tig, wm, wn);
    }

    // epilogue: + bias, relu, store (f contiguous)
    #pragma unroll
    for (int mi = 0; mi < 2; ++mi)
        #pragma unroll
        for (int h = 0; h < 2; ++h) {
            const int l = l0 + wm * 32 + mi * 16 + gid + 8 * h;
            float* Orow = out + ((size_t)b * SEQL + l) * NF + f0;
            #pragma unroll
            for (int ni = 0; ni < 8; ++ni) {
                const int fl = wn * 64 + ni * 8 + 2 * tig;
                const float2 bv = *(const float2*)(bias + f0 + fl);
                const float* c = &acc[(mi * 8 + ni) * 4 + 2 * h];
                float2 o;
                o.x = fmaxf(c[0] + bv.x, 0.f);
                o.y = fmaxf(c[1] + bv.y, 0.f);
                *(float2*)(Orow + fl) = o;
            }
        }
}

// ---------------------------------------------------------------------------
// kernel_launch: prep1 -> prep2 -> gemm_w -> conv (stream-ordered, capturable)
// Inputs: x, z, U, V, B_w, b, kernel_size(ignored; KSZ=3)
// ---------------------------------------------------------------------------
extern "C" void kernel_launch(void* const* d_in, const int* in_sizes, int n_in,
                              void* d_out, int out_size)
{
    (void)in_sizes; (void)n_in; (void)out_size;
    const float* x    = (const float*)d_in[0];
    const float* z    = (const float*)d_in[1];
    const float* U    = (const float*)d_in[2];
    const float* V    = (const float*)d_in[3];
    const float* Bw   = (const float*)d_in[4];
    const float* bias = (const float*)d_in[5];
    float* out = (float*)d_out;

    static bool attr_done = false;
    if (!attr_done) {
        cudaFuncSetAttribute(gemm_w,   cudaFuncAttributeMaxDynamicSharedMemorySize, SMEM_BYTES);
        cudaFuncSetAttribute(conv_mma, cudaFuncAttributeMaxDynamicSharedMemorySize, SMEM_BYTES);
        attr_done = true;
    }

    prep1<<<2048, 256>>>(x, z, V);
    prep2<<<dim3(NB, DIN / 4), 256>>>(U);
    gemm_w<<<dim3(NJ / 128, DIN / 128, NB), 256, SMEM_BYTES>>>(Bw);
    conv_mma<<<dim3(NF / 128, SEQL / 128, NB), 256, SMEM_BYTES>>>(bias, out);
}

// round 10
// speedup vs baseline: 1.3718x; 1.3062x over previous
#include <cuda_runtime.h>
#include <cstdint>
#include <math.h>

// Problem constants
#define NB   64
#define SEQL 512
#define DIN  256
#define NF   256
#define KSZ  3
#define NJ   768                 // KSZ*NF

// Static device scratch (no allocs allowed)
__device__ float g_sig[NB * DIN];                  // sigmoid(z)
__device__ float g_Vr [NJ * DIN];                  // rna(V)^T          [j][e]
__device__ float g_xr [NB * SEQL * DIN];           // rna(x)
__device__ float g_Ub [NB * DIN * DIN];            // rna(U * sig_b)    [b][d][e]
__device__ float g_Wt [NB * NF * NJ];              // weights           [b][f][kd] (kd = k*256+d)

// ---------------------------------------------------------------------------
// Helpers
// ---------------------------------------------------------------------------
__device__ __forceinline__ uint32_t smem_u32(const void* p) {
    uint32_t a;
    asm("{ .reg .u64 t; cvta.to.shared.u64 t, %1; cvt.u32.u64 %0, t; }"
        : "=r"(a) : "l"(p));
    return a;
}
__device__ __forceinline__ float rna(float x) {
    uint32_t u;
    asm("cvt.rna.tf32.f32 %0, %1;" : "=r"(u) : "f"(x));
    return __uint_as_float(u);
}
#define CP16(dst, src) \
    asm volatile("cp.async.cg.shared.global [%0], [%1], 16;" :: "r"(dst), "l"(src))
#define CP16Z(dst, src, sz) \
    asm volatile("cp.async.cg.shared.global [%0], [%1], 16, %2;" :: "r"(dst), "l"(src), "r"(sz))
#define CP_COMMIT() asm volatile("cp.async.commit_group;")
#define CP_WAIT1()  asm volatile("cp.async.wait_group 1;" ::: "memory")
#define CP_WAIT0()  asm volatile("cp.async.wait_group 0;" ::: "memory")

#define LDM4(r0, r1, r2, r3, addr) \
    asm volatile("ldmatrix.sync.aligned.m8n8.x4.shared.b16 {%0,%1,%2,%3}, [%4];" \
        : "=r"(r0), "=r"(r1), "=r"(r2), "=r"(r3) : "r"(addr))

// ---------------------------------------------------------------------------
// SMEM stage (32 KB; three stages = 96 KB dynamic):
//   As: 128 rows (M) x 32 floats (K), 128 B/row; 16B chunk c (0..7) of row r
//       at r*128 + ((c ^ (r&7))<<4)                          [16384 B]
//   Bs: 128 rows (N) x 32 floats (K), same layout/swizzle    [16384 B]
// ldmatrix: each 8-address group hits 8 distinct swizzled chunks -> no
// bank conflicts (chunk = c ^ (r&7) is a bijection over r&7).
// ---------------------------------------------------------------------------
#define STAGE_BYTES 32768
#define NSTAGE      3
#define SMEM_BYTES  (STAGE_BYTES * NSTAGE)

// One BK=32 slab: warp tile 32(M) x 64(N), m16n8k8 tf32, acc[64].
// A/B fragments fetched via ldmatrix.x4 (24 per tile vs 96 scalar LDS).
__device__ __forceinline__ void tile_mma(float* __restrict__ acc,
                                         uint32_t Aa, uint32_t Ba,
                                         int lane, int wm, int wn)
{
    const uint32_t s     = lane & 7;
    const uint32_t ahalf = (lane >> 4) & 1;        // A: chunk parity
    const uint32_t bhalf = (lane >> 3) & 1;        // B: chunk parity
    const uint32_t abase = Aa + (wm * 32 + (lane & 15)) * 128;
    const uint32_t bbase = Ba + (wn * 64 + ((lane >> 4) & 1) * 8 + (lane & 7)) * 128;

    #pragma unroll
    for (int ks = 0; ks < 4; ++ks) {
        const uint32_t ca = ((2 * ks + ahalf) ^ s) << 4;
        const uint32_t cb = ((2 * ks + bhalf) ^ s) << 4;

        uint32_t a0[4], a1[4];
        LDM4(a0[0], a0[1], a0[2], a0[3], abase + ca);           // mi=0 (rows m..m+15)
        LDM4(a1[0], a1[1], a1[2], a1[3], abase + 2048 + ca);    // mi=1 (+16 rows)

        uint32_t bf[4][4];
        #pragma unroll
        for (int q = 0; q < 4; ++q)
            LDM4(bf[q][0], bf[q][1], bf[q][2], bf[q][3], bbase + q * 2048 + cb);

        #pragma unroll
        for (int q = 0; q < 4; ++q)
            #pragma unroll
            for (int p = 0; p < 2; ++p) {
                const int ni = 2 * q + p;
                const uint32_t b0 = bf[q][2 * p], b1 = bf[q][2 * p + 1];
                {
                    float* c = &acc[ni * 4];
                    asm volatile(
                        "mma.sync.aligned.m16n8k8.row.col.f32.tf32.tf32.f32 "
                        "{%0,%1,%2,%3}, {%4,%5,%6,%7}, {%8,%9}, {%0,%1,%2,%3};"
                        : "+f"(c[0]), "+f"(c[1]), "+f"(c[2]), "+f"(c[3])
                        : "r"(a0[0]), "r"(a0[1]), "r"(a0[2]), "r"(a0[3]),
                          "r"(b0), "r"(b1));
                }
                {
                    float* c = &acc[(8 + ni) * 4];
                    asm volatile(
                        "mma.sync.aligned.m16n8k8.row.col.f32.tf32.tf32.f32 "
                        "{%0,%1,%2,%3}, {%4,%5,%6,%7}, {%8,%9}, {%0,%1,%2,%3};"
                        : "+f"(c[0]), "+f"(c[1]), "+f"(c[2]), "+f"(c[3])
                        : "r"(a1[0]), "r"(a1[1]), "r"(a1[2]), "r"(a1[3]),
                          "r"(b0), "r"(b1));
                }
            }
    }
}

// ---------------------------------------------------------------------------
// Prep 1: rna(x) -> g_xr, rna(V)^T -> g_Vr ([j][e]), sigmoid(z) -> g_sig
// ---------------------------------------------------------------------------
__global__ void prep1(const float* __restrict__ x,
                      const float* __restrict__ z,
                      const float* __restrict__ V)
{
    const int tid = blockIdx.x * blockDim.x + threadIdx.x;
    const int nth = gridDim.x * blockDim.x;
    const float4* x4 = (const float4*)x;
    float4* xr4 = (float4*)g_xr;
    for (int i = tid; i < NB * SEQL * DIN / 4; i += nth) {
        float4 v = x4[i];
        v.x = rna(v.x); v.y = rna(v.y); v.z = rna(v.z); v.w = rna(v.w);
        xr4[i] = v;
    }
    // transpose V: g_Vr[j][e] = rna(V[e][j]); writes coalesced
    for (int i = tid; i < NJ * DIN; i += nth) {
        const int j = i >> 8, e = i & 255;
        g_Vr[i] = rna(V[(size_t)e * NJ + j]);
    }
    for (int i = tid; i < NB * DIN; i += nth)
        g_sig[i] = 1.f / (1.f + expf(-z[i]));
}

// ---------------------------------------------------------------------------
// Prep 2: g_Ub[b][d][e] = rna(U[d][e] * sig[b][e])
// ---------------------------------------------------------------------------
__global__ void prep2(const float* __restrict__ U)
{
    const int b = blockIdx.x, dblk = blockIdx.y;
    const int t = threadIdx.x;
    const int d  = dblk * 4 + (t >> 6);
    const int e4 = (t & 63) * 4;
    const float4 u = *(const float4*)(U + (size_t)d * DIN + e4);
    const float4 s = *(const float4*)(g_sig + b * DIN + e4);
    float4 o;
    o.x = rna(u.x * s.x); o.y = rna(u.y * s.y);
    o.z = rna(u.z * s.z); o.w = rna(u.w * s.w);
    *(float4*)(g_Ub + ((size_t)(b * DIN + d)) * DIN + e4) = o;
}

// ---------------------------------------------------------------------------
// GEMM1: per b: D[d][j] = sum_e Ub[b][d][e] * Vr[j][e]; W = D + Bw
//   CTA 128x128, 256 thr (8 warps, 4x2 of 32x64), BK=32, K=256 (8 tiles)
//   store g_Wt[b][f][kq*256+d] (rna-rounded)
// ---------------------------------------------------------------------------
__global__ __launch_bounds__(256, 2)
void gemm_w(const float* __restrict__ Bw)
{
    extern __shared__ char sm[];
    const int b = blockIdx.z, m0 = blockIdx.y * 128, n0 = blockIdx.x * 128;
    const int kq = n0 >> 8, f0 = n0 & 255;
    const int tid = (int)threadIdx.x, wid = tid >> 5, lane = tid & 31;
    const int gid = lane >> 2, tig = lane & 3, wm = wid & 3, wn = wid >> 2;

    const uint32_t sb = smem_u32(sm);
    const float* Asrc = g_Ub + (size_t)b * DIN * DIN + (size_t)m0 * DIN;
    const float* Bsrc = g_Vr + (size_t)n0 * DIN;

    float acc[64];
    #pragma unroll
    for (int i = 0; i < 64; ++i) acc[i] = 0.f;

    auto load = [&](int t) {
        const int e0 = t * 32, st = t % NSTAGE;
        const uint32_t ab = sb + st * STAGE_BYTES;
        const uint32_t bb = ab + 16384;
        #pragma unroll
        for (int i = 0; i < 4; ++i) {
            const int c = tid + i * 256;
            const int r = c >> 3, c4 = c & 7;
            CP16(ab + r * 128 + ((c4 ^ (r & 7)) << 4),
                 Asrc + (size_t)r * DIN + e0 + c4 * 4);
        }
        #pragma unroll
        for (int i = 0; i < 4; ++i) {
            const int c = tid + i * 256;
            const int r = c >> 3, c4 = c & 7;
            CP16(bb + r * 128 + ((c4 ^ (r & 7)) << 4),
                 Bsrc + (size_t)r * DIN + e0 + c4 * 4);
        }
        CP_COMMIT();
    };

    load(0); load(1);
    for (int t = 0; t < 8; ++t) {
        if (t < 7) CP_WAIT1(); else CP_WAIT0();
        __syncthreads();
        if (t + 2 < 8) load(t + 2);
        const uint32_t stg = sb + (t % NSTAGE) * STAGE_BYTES;
        tile_mma(acc, stg, stg + 16384, lane, wm, wn);
    }

    // epilogue: + Bw, rna, store g_Wt[b][f][kq*256+d]
    #pragma unroll
    for (int mi = 0; mi < 2; ++mi)
        #pragma unroll
        for (int h = 0; h < 2; ++h) {
            const int d = m0 + wm * 32 + mi * 16 + gid + 8 * h;
            const float* BwRow = Bw + (size_t)d * NJ + n0;
            float* Wcol = g_Wt + (size_t)b * NF * NJ + (size_t)kq * DIN + d;
            #pragma unroll
            for (int ni = 0; ni < 8; ++ni) {
                const int jl = wn * 64 + ni * 8 + 2 * tig;
                const float2 bw = *(const float2*)(BwRow + jl);
                const float* c = &acc[(mi * 8 + ni) * 4 + 2 * h];
                Wcol[(size_t)(f0 + jl)     * NJ] = rna(c[0] + bw.x);
                Wcol[(size_t)(f0 + jl + 1) * NJ] = rna(c[1] + bw.y);
            }
        }
}

// ---------------------------------------------------------------------------
// Conv: per b: out[l][f] = relu( sum_{kd<768} A[l][kd] * Wt[b][f][kd] + bias )
//   A[l][kd] = g_xr[b] flat at (l-1)*256 + kd, zero outside [0, 512*256)
//   CTA 128x128, 256 thr (8 warps, 4x2 of 32x64), BK=32, K=768 (24 tiles)
// ---------------------------------------------------------------------------
__global__ __launch_bounds__(256, 2)
void conv_mma(const float* __restrict__ bias, float* __restrict__ out)
{
    extern __shared__ char sm[];
    const int b = blockIdx.z, l0 = blockIdx.y * 128, f0 = blockIdx.x * 128;
    const int tid = (int)threadIdx.x, wid = tid >> 5, lane = tid & 31;
    const int gid = lane >> 2, tig = lane & 3, wm = wid & 3, wn = wid >> 2;

    const uint32_t sb = smem_u32(sm);
    const float* xb = g_xr + (size_t)b * SEQL * DIN;
    const float* Wsrc = g_Wt + ((size_t)b * NF + f0) * NJ;

    float acc[64];
    #pragma unroll
    for (int i = 0; i < 64; ++i) acc[i] = 0.f;

    auto load = [&](int t) {
        const int e0 = t * 32, st = t % NSTAGE;
        const uint32_t ab = sb + st * STAGE_BYTES;
        const uint32_t bb = ab + 16384;
        #pragma unroll
        for (int i = 0; i < 4; ++i) {
            const int c = tid + i * 256;
            const int r = c >> 3, c4 = c & 7;
            const int idx = (l0 + r - 1) * DIN + e0 + c4 * 4;
            const unsigned ok = ((unsigned)idx < (unsigned)(SEQL * DIN));
            const float* src = xb + (ok ? idx : 0);
            CP16Z(ab + r * 128 + ((c4 ^ (r & 7)) << 4), src, ok ? 16u : 0u);
        }
        #pragma unroll
        for (int i = 0; i < 4; ++i) {
            const int c = tid + i * 256;
            const int r = c >> 3, c4 = c & 7;
            CP16(bb + r * 128 + ((c4 ^ (r & 7)) << 4),
                 Wsrc + (size_t)r * NJ + e0 + c4 * 4);
        }
        CP_COMMIT();
    };

    load(0); load(1);
    for (int t = 0; t < 24; ++t) {
        if (t < 23) CP_WAIT1(); else CP_WAIT0();
        __syncthreads();
        if (t + 2 < 24) load(t + 2);
        const uint32_t stg = sb + (t % NSTAGE) * STAGE_BYTES;
        tile_mma(acc, stg, stg + 16384, lane, wm, wn);
    }

    // epilogue: + bias, relu, store (f contiguous)
    #pragma unroll
    for (int mi = 0; mi < 2; ++mi)
        #pragma unroll
        for (int h = 0; h < 2; ++h) {
            const int l = l0 + wm * 32 + mi * 16 + gid + 8 * h;
            float* Orow = out + ((size_t)b * SEQL + l) * NF + f0;
            #pragma unroll
            for (int ni = 0; ni < 8; ++ni) {
                const int fl = wn * 64 + ni * 8 + 2 * tig;
                const float2 bv = *(const float2*)(bias + f0 + fl);
                const float* c = &acc[(mi * 8 + ni) * 4 + 2 * h];
                float2 o;
                o.x = fmaxf(c[0] + bv.x, 0.f);
                o.y = fmaxf(c[1] + bv.y, 0.f);
                *(float2*)(Orow + fl) = o;
            }
        }
}

// ---------------------------------------------------------------------------
// kernel_launch: prep1 -> prep2 -> gemm_w -> conv (stream-ordered, capturable)
// Inputs: x, z, U, V, B_w, b, kernel_size(ignored; KSZ=3)
// ---------------------------------------------------------------------------
extern "C" void kernel_launch(void* const* d_in, const int* in_sizes, int n_in,
                              void* d_out, int out_size)
{
    (void)in_sizes; (void)n_in; (void)out_size;
    const float* x    = (const float*)d_in[0];
    const float* z    = (const float*)d_in[1];
    const float* U    = (const float*)d_in[2];
    const float* V    = (const float*)d_in[3];
    const float* Bw   = (const float*)d_in[4];
    const float* bias = (const float*)d_in[5];
    float* out = (float*)d_out;

    static bool attr_done = false;
    if (!attr_done) {
        cudaFuncSetAttribute(gemm_w,   cudaFuncAttributeMaxDynamicSharedMemorySize, SMEM_BYTES);
        cudaFuncSetAttribute(conv_mma, cudaFuncAttributeMaxDynamicSharedMemorySize, SMEM_BYTES);
        attr_done = true;
    }

    prep1<<<2048, 256>>>(x, z, V);
    prep2<<<dim3(NB, DIN / 4), 256>>>(U);
    gemm_w<<<dim3(NJ / 128, DIN / 128, NB), 256, SMEM_BYTES>>>(Bw);
    conv_mma<<<dim3(NF / 128, SEQL / 128, NB), 256, SMEM_BYTES>>>(bias, out);
}